// round 8
// baseline (speedup 1.0000x reference)
#include <cuda_runtime.h>
#include <cuda_bf16.h>

// Problem constants (fixed by reference)
#define BN    4096
#define NTOTN 100000
#define DN    32
#define HN    64
#define TN    8
#define NEGV  (-1e9f)

#define EPB   8     // elements per block (1 warp each)
#define WST   68    // smem row stride (bank-conflict padding)

// 256 threads = 8 warps = 8 elements, lockstepped per rollout step.
// Phase 1 (per live warp): keys gather + scores + LN + argmax/log-softmax.
// Phase 2 (whole block): batched hidden update using smem-staged W^T,
// warp w computes output cols [8w,8w+8) for ALL 8 elements -> W read once
// per block-step instead of once per element-step.
__global__ __launch_bounds__(256, 4)
void gfn_rollout_kernel(const float* __restrict__ qt,         // [B,64]
                        const int*   __restrict__ nbr,        // [NTOT,32]
                        const int*   __restrict__ start,      // [B]
                        const void*  __restrict__ evp,        // [NTOT,32] bool (dtype detected)
                        const float* __restrict__ keys,       // [NTOT,32,64]
                        const float* __restrict__ Wi,         // [64,64]
                        const float* __restrict__ Wh,         // [64,64]
                        const float* __restrict__ Wk,         // [64,64]
                        const float* __restrict__ g,          // [66]
                        const float* __restrict__ be,         // [66]
                        const float* __restrict__ sw,         // [66]
                        const float* __restrict__ sbp,        // [1]
                        const float* __restrict__ temp,       // [1]
                        float* __restrict__ out)
{
    __shared__ __align__(16) float WhT[HN * WST];   // WhT[c*WST + i] = Wh[i][c]
    __shared__ __align__(16) float WkT[HN * WST];
    __shared__ __align__(16) float Hs[EPB * WST];   // hidden per element
    __shared__ __align__(16) float Ss[EPB * WST];   // selected key row per element
    __shared__ int s_adv[EPB];

    const int tid   = threadIdx.x;
    const int wid   = tid >> 5;
    const int lane  = tid & 31;
    const int q     = lane & 15;
    const int hh    = lane >> 4;
    const int myrow = 2 * q + hh;
    const int b     = blockIdx.x * EPB + wid;

    const float tclamp = fmaxf(temp[0], 1e-5f);
    const float itc    = 1.0f / tclamp;
    const float stop_b = sbp[0];

    // ---- stage W^T into shared ----
    for (int idx = tid; idx < HN * HN; idx += 256) {
        int i = idx >> 6, c = idx & 63;
        WhT[c * WST + i] = __ldg(&Wh[idx]);
        WkT[c * WST + i] = __ldg(&Wk[idx]);
    }
    if (lane == 0) s_adv[wid] = 0;

    // ---- detect edge_valid element width (word-typed int32/float32 vs byte bool) ----
    bool word_typed;
    {
        const unsigned* wv = (const unsigned*)evp;
        bool ok = true;
        #pragma unroll
        for (int i = 0; i < 4; i++) {
            unsigned v = wv[i * 32 + lane];
            ok &= (v == 0u || v == 1u || v == 0x3F800000u);
        }
        word_typed = __all_sync(0xffffffffu, ok);
    }
    const unsigned*      ev32 = (const unsigned*)evp;
    const unsigned char* ev8  = (const unsigned char*)evp;

    // ---- fold LN constants: ((c*rstd)*g+be)*sw == rstd*(Sg - mu*Gsum) + bsum ----
    const float gsw0 = __ldg(&g[lane])      * __ldg(&sw[lane]);
    const float gsw1 = __ldg(&g[lane + 32]) * __ldg(&sw[lane + 32]);
    float gsw64 = 0.f, gsw65 = 0.f;
    float bsum, Gsum;
    {
        float bs = __ldg(&be[lane]) * __ldg(&sw[lane])
                 + __ldg(&be[lane + 32]) * __ldg(&sw[lane + 32]);
        float gs = gsw0 + gsw1;
        if (lane == 0) {
            gsw64 = __ldg(&g[64]) * __ldg(&sw[64]);
            gsw65 = __ldg(&g[65]) * __ldg(&sw[65]);
            bs += __ldg(&be[64]) * __ldg(&sw[64]) + __ldg(&be[65]) * __ldg(&sw[65]);
        }
        #pragma unroll
        for (int o = 16; o; o >>= 1) {
            bs += __shfl_xor_sync(~0u, bs, o);
            gs += __shfl_xor_sync(~0u, gs, o);
        }
        bsum = bs; Gsum = gs;   // Gsum excludes gsw64/65 contributions times centered e...
    }
    // NOTE: Gsum must include gsw64+gsw65 (they multiply (e-mu); the -mu part needs them).
    {
        float extra = (lane == 0) ? (gsw64 + gsw65) : 0.f;
        #pragma unroll
        for (int o = 16; o; o >>= 1) extra += __shfl_xor_sync(~0u, extra, o);
        Gsum += extra;
    }

    // ---- init hidden = tanh(q[b] @ W_init) (per warp, Wi from gmem, once) ----
    {
        float* hb = Hs + wid * WST;
        hb[lane]      = qt[b * HN + lane];
        hb[lane + 32] = qt[b * HN + lane + 32];
        __syncwarp();
        float4 acc = make_float4(0.f, 0.f, 0.f, 0.f);
        #pragma unroll
        for (int it = 0; it < 32; it++) {
            int i = 2 * it + hh;
            float hv = hb[i];
            float4 wv = __ldg((const float4*)(Wi + i * HN + 4 * q));
            acc.x += hv * wv.x; acc.y += hv * wv.y;
            acc.z += hv * wv.z; acc.w += hv * wv.w;
        }
        acc.x += __shfl_xor_sync(0xffffffffu, acc.x, 16);
        acc.y += __shfl_xor_sync(0xffffffffu, acc.y, 16);
        acc.z += __shfl_xor_sync(0xffffffffu, acc.z, 16);
        acc.w += __shfl_xor_sync(0xffffffffu, acc.w, 16);
        __syncwarp();
        if (hh == 0) {
            float4 t4 = make_float4(tanhf(acc.x), tanhf(acc.y), tanhf(acc.z), tanhf(acc.w));
            *(float4*)(hb + 4 * q) = t4;
        }
        __syncwarp();
    }

    int   curr     = start[b];
    float lp_total = 0.f;
    int   nmoves   = 0;
    int   tstop    = TN;
    bool  live     = true;

    // output sections (float32, concatenated reference outputs)
    float* outA   = out;                          // actions_seq  [B,9]
    float* outTot = out + BN * 9;                 // log_pf_total [B]
    float* outS   = out + BN * 9 + BN;            // log_pf_steps [B,9]
    float* outNM  = out + BN * 9 + BN + BN * 9;   // num_moves    [B]

    // matvec lane mapping: element e, column pair cp
    const int me  = lane >> 2;
    const int c0  = 8 * wid + 2 * (lane & 3);

    for (int t = 0; t <= TN; t++) {
        if (live) {
            const float4* kb4 = (const float4*)(keys + (size_t)curr * (DN * HN));

            // early independent loads
            int nb = __ldg(&nbr[(size_t)curr * DN + myrow]);
            size_t evi = (size_t)curr * DN + myrow;
            int vraw = word_typed ? (ev32[evi] != 0u) : (ev8[evi] != 0);

            // fused gather + partial dots
            float4 h4 = *(const float4*)(Hs + wid * WST + 4 * q);
            float p[16];
            #pragma unroll
            for (int it = 0; it < 16; it++) {
                float4 v = __ldg(&kb4[it * 32 + lane]);
                p[it] = v.x * h4.x + v.y * h4.y + v.z * h4.z + v.w * h4.w;
            }
            // transpose-reduce: lane (q,hh) ends with score of row 2q+hh
            #pragma unroll
            for (int k = 8; k >= 1; k >>= 1) {
                bool hi = (q & k) != 0;
                #pragma unroll
                for (int i = 0; i < 8; i++) {
                    if (i < k) {
                        float send = hi ? p[i] : p[i + k];
                        float recv = __shfl_xor_sync(0xffffffffu, send, k);
                        p[i] = (hi ? p[i + k] : p[i]) + recv;
                    }
                }
            }
            float sc = p[0];

            int vd = (t < TN) ? vraw : 0;
            unsigned vm = __ballot_sync(0xffffffffu, vd);
            float has_edge = vm ? 1.f : 0.f;
            float logit = (vd ? sc : NEGV) * itc;

            // fused single-pass LN (S1, S2, Sg reduced together)
            float x0 = Hs[wid * WST + lane], x1 = Hs[wid * WST + lane + 32];
            float e64 = (float)t / (float)TN;
            float e65 = has_edge;
            float s1 = x0 + x1;
            float s2 = x0 * x0 + x1 * x1;
            float sg = x0 * gsw0 + x1 * gsw1;
            if (lane == 0) {
                s1 += e64 + e65;
                s2 += e64 * e64 + e65 * e65;
                sg += e64 * gsw64 + e65 * gsw65;
            }
            #pragma unroll
            for (int o = 16; o; o >>= 1) {
                s1 += __shfl_xor_sync(~0u, s1, o);
                s2 += __shfl_xor_sync(~0u, s2, o);
                sg += __shfl_xor_sync(~0u, sg, o);
            }
            float mu = s1 * (1.f / 66.f);
            float var = s2 * (1.f / 66.f) - mu * mu;
            float rstd = rsqrtf(var + 1e-5f);
            float stop_logit = ((sg - mu * Gsum) * rstd + bsum + stop_b) * itc;

            // argmax (first-max by row id), then stop (strict >)
            float bv = logit; int bi = myrow;
            #pragma unroll
            for (int o = 16; o; o >>= 1) {
                float ov = __shfl_xor_sync(~0u, bv, o);
                int   oi = __shfl_xor_sync(~0u, bi, o);
                if (ov > bv || (ov == bv && oi < bi)) { bv = ov; bi = oi; }
            }
            int action; float chosen;
            if (stop_logit > bv) { action = DN; chosen = stop_logit; }
            else                 { action = bi; chosen = bv; }

            // log-softmax denominator over 33
            float m = fmaxf(bv, stop_logit);
            float es = expf(logit - m);
            #pragma unroll
            for (int o = 16; o; o >>= 1) es += __shfl_xor_sync(~0u, es, o);
            es += expf(stop_logit - m);
            float lp = chosen - (m + logf(es));

            bool chose_stop = (action == DN);
            int  a = chose_stop ? (DN - 1) : action;
            int  act_rec = chose_stop ? -1 : curr * DN + a;

            if (lane == 0) {
                outA[b * 9 + t] = (float)act_rec;
                outS[b * 9 + t] = lp;
            }
            lp_total += lp;

            if (chose_stop) {
                live = false;
                tstop = t;
                if (lane == 0) s_adv[wid] = 0;
            } else {
                nmoves++;
                int src_lane = (a >> 1) | ((a & 1) << 4);
                int tail = __shfl_sync(0xffffffffu, nb, src_lane);
                if (lane < 16) {
                    float4 sv = __ldg(&kb4[a * 16 + lane]);
                    *(float4*)(Ss + wid * WST + 4 * lane) = sv;
                }
                if (lane == 0) s_adv[wid] = 1;
                curr = tail;
            }
        }

        int nlive = __syncthreads_count((int)live);
        if (nlive == 0) break;

        // ---- batched hidden update: warp wid computes cols [8w,8w+8) for all elems ----
        {
            const float4* H4 = (const float4*)(Hs + me * WST);
            const float4* S4 = (const float4*)(Ss + me * WST);
            const float4* A0 = (const float4*)(WhT + c0 * WST);
            const float4* A1 = (const float4*)(WhT + (c0 + 1) * WST);
            const float4* B0 = (const float4*)(WkT + c0 * WST);
            const float4* B1 = (const float4*)(WkT + (c0 + 1) * WST);
            float acc0 = 0.f, acc1 = 0.f;
            #pragma unroll
            for (int i4 = 0; i4 < 16; i4++) {
                float4 hv = H4[i4];
                float4 sv = S4[i4];
                float4 a0 = A0[i4];
                float4 b0 = B0[i4];
                acc0 += hv.x * a0.x + hv.y * a0.y + hv.z * a0.z + hv.w * a0.w
                      + sv.x * b0.x + sv.y * b0.y + sv.z * b0.z + sv.w * b0.w;
                float4 a1 = A1[i4];
                float4 b1 = B1[i4];
                acc1 += hv.x * a1.x + hv.y * a1.y + hv.z * a1.z + hv.w * a1.w
                      + sv.x * b1.x + sv.y * b1.y + sv.z * b1.z + sv.w * b1.w;
            }
            int adv = s_adv[me];
            __syncthreads();
            if (adv) {
                Hs[me * WST + c0]     = tanhf(acc0);
                Hs[me * WST + c0 + 1] = tanhf(acc1);
            }
            __syncthreads();
        }
    }

    // ---- fill forced-stopped tail steps + totals ----
    if (lane == 0) {
        for (int tt = tstop + 1; tt <= TN; tt++) {
            outA[b * 9 + tt] = -1.f;
            outS[b * 9 + tt] = 0.f;
        }
        outTot[b] = lp_total;
        outNM[b]  = (float)nmoves;
    }
}

extern "C" void kernel_launch(void* const* d_in, const int* in_sizes, int n_in,
                              void* d_out, int out_size)
{
    const float* q     = (const float*)d_in[0];
    const int*   nbr   = (const int*)d_in[1];
    const int*   start = (const int*)d_in[2];
    const void*  ev    = (const void*)d_in[3];
    const float* keys  = (const float*)d_in[4];
    const float* Wi    = (const float*)d_in[5];
    const float* Wh    = (const float*)d_in[6];
    const float* Wk    = (const float*)d_in[7];
    const float* g     = (const float*)d_in[8];
    const float* be    = (const float*)d_in[9];
    const float* sw    = (const float*)d_in[10];
    const float* sb    = (const float*)d_in[11];
    const float* temp  = (const float*)d_in[12];
    float* out = (float*)d_out;

    dim3 grid(BN / EPB);
    dim3 block(256);
    gfn_rollout_kernel<<<grid, block>>>(q, nbr, start, ev, keys,
                                        Wi, Wh, Wk, g, be, sw, sb, temp, out);
}

// round 9
// speedup vs baseline: 2.2055x; 2.2055x over previous
#include <cuda_runtime.h>
#include <cuda_bf16.h>

// Problem constants (fixed by reference)
#define BN    4096
#define NTOTN 100000
#define DN    32
#define HN    64
#define TN    8
#define NEGV  (-1e9f)

// One warp per batch element, 4 warps/block, 7 blocks/SM -> whole grid resident
// in a single wave (148*7*4 = 4144 >= 4096 warps).
// Lane layout: q = lane&15 (chunk), h = lane>>4 (row parity); myrow = 2q+h.
// The h@Wh half of the hidden update is hoisted BEFORE the LN/argmax/softmax
// shuffle chain (independent of it); only sel@Wk remains on the dependent path.
__global__ __launch_bounds__(128, 7)
void gfn_rollout_kernel(const float* __restrict__ qt,         // [B,64]
                        const int*   __restrict__ nbr,        // [NTOT,32]
                        const int*   __restrict__ start,      // [B]
                        const void*  __restrict__ evp,        // [NTOT,32] bool (dtype detected)
                        const float* __restrict__ keys,       // [NTOT,32,64]
                        const float* __restrict__ Wi,         // [64,64]
                        const float* __restrict__ Wh,         // [64,64]
                        const float* __restrict__ Wk,         // [64,64]
                        const float* __restrict__ g,          // [66]
                        const float* __restrict__ be,         // [66]
                        const float* __restrict__ sw,         // [66]
                        const float* __restrict__ sbp,        // [1]
                        const float* __restrict__ temp,       // [1]
                        float* __restrict__ out)
{
    __shared__ float shid[4][HN];   // hidden per warp
    __shared__ float ssel[4][HN];   // selected key row per warp

    const int w     = threadIdx.x >> 5;
    const int lane  = threadIdx.x & 31;
    const int q     = lane & 15;
    const int hh    = lane >> 4;
    const int myrow = 2 * q + hh;
    const int b     = blockIdx.x * 4 + w;

    float* sh = shid[w];
    float* ss = ssel[w];

    const float tclamp = fmaxf(temp[0], 1e-5f);
    const float itc    = 1.0f / tclamp;
    const float stop_b = sbp[0];

    // ---- detect edge_valid element width (word-typed int32/float32 vs byte bool) ----
    bool word_typed;
    {
        const unsigned* wv = (const unsigned*)evp;
        bool ok = true;
        #pragma unroll
        for (int i = 0; i < 4; i++) {
            unsigned v = wv[i * 32 + lane];
            ok &= (v == 0u || v == 1u || v == 0x3F800000u);
        }
        word_typed = __all_sync(0xffffffffu, ok);
    }
    const unsigned*      ev32 = (const unsigned*)evp;
    const unsigned char* ev8  = (const unsigned char*)evp;

    // ---- fold LN constants: ((c*rstd)*g+be)*sw == rstd*(Sg - mu*Gsum) + bsum ----
    const float gsw0 = __ldg(&g[lane])      * __ldg(&sw[lane]);
    const float gsw1 = __ldg(&g[lane + 32]) * __ldg(&sw[lane + 32]);
    float gsw64 = 0.f, gsw65 = 0.f;
    float bsum, Gsum;
    {
        float bs = __ldg(&be[lane]) * __ldg(&sw[lane])
                 + __ldg(&be[lane + 32]) * __ldg(&sw[lane + 32]);
        float gs = gsw0 + gsw1;
        if (lane == 0) {
            gsw64 = __ldg(&g[64]) * __ldg(&sw[64]);
            gsw65 = __ldg(&g[65]) * __ldg(&sw[65]);
            bs += __ldg(&be[64]) * __ldg(&sw[64]) + __ldg(&be[65]) * __ldg(&sw[65]);
            gs += gsw64 + gsw65;
        }
        #pragma unroll
        for (int o = 16; o; o >>= 1) {
            bs += __shfl_xor_sync(~0u, bs, o);
            gs += __shfl_xor_sync(~0u, gs, o);
        }
        bsum = bs; Gsum = gs;
    }

    // ---- init hidden = tanh(q[b] @ W_init), cooperative row-major matvec ----
    sh[lane]      = qt[b * HN + lane];
    sh[lane + 32] = qt[b * HN + lane + 32];
    __syncwarp();
    {
        float4 acc = make_float4(0.f, 0.f, 0.f, 0.f);
        #pragma unroll
        for (int it = 0; it < 32; it++) {
            int i = 2 * it + hh;
            float hv = sh[i];
            float4 wv = __ldg((const float4*)(Wi + i * HN + 4 * q));
            acc.x += hv * wv.x; acc.y += hv * wv.y;
            acc.z += hv * wv.z; acc.w += hv * wv.w;
        }
        acc.x += __shfl_xor_sync(0xffffffffu, acc.x, 16);
        acc.y += __shfl_xor_sync(0xffffffffu, acc.y, 16);
        acc.z += __shfl_xor_sync(0xffffffffu, acc.z, 16);
        acc.w += __shfl_xor_sync(0xffffffffu, acc.w, 16);
        __syncwarp();
        if (hh == 0) {
            float4 t4 = make_float4(tanhf(acc.x), tanhf(acc.y), tanhf(acc.z), tanhf(acc.w));
            *(float4*)(sh + 4 * q) = t4;
        }
        __syncwarp();
    }

    int   curr     = start[b];
    float lp_total = 0.f;
    int   nmoves   = 0;

    // output sections (float32, concatenated reference outputs)
    float* outA   = out;                          // actions_seq  [B,9]
    float* outTot = out + BN * 9;                 // log_pf_total [B]
    float* outS   = out + BN * 9 + BN;            // log_pf_steps [B,9]
    float* outNM  = out + BN * 9 + BN + BN * 9;   // num_moves    [B]

    int t = 0;
    for (t = 0; t <= TN; t++) {
        const float4* kb4 = (const float4*)(keys + (size_t)curr * (DN * HN));

        // ---- early independent loads: nbr row (tail via shuffle later) + validity ----
        int nb = __ldg(&nbr[(size_t)curr * DN + myrow]);
        size_t evi = (size_t)curr * DN + myrow;
        int vraw = word_typed ? (ev32[evi] != 0u) : (ev8[evi] != 0);

        // ---- fused gather + partial dots: p[it] = <keys[2it+hh], hidden>[chunk q] ----
        float4 h4 = *(const float4*)(sh + 4 * q);
        float p[16];
        #pragma unroll
        for (int it = 0; it < 16; it++) {
            float4 v = __ldg(&kb4[it * 32 + lane]);
            p[it] = v.x * h4.x + v.y * h4.y + v.z * h4.z + v.w * h4.w;
        }

        // ---- transpose-reduce over chunks (within each 16-lane half) ----
        #pragma unroll
        for (int k = 8; k >= 1; k >>= 1) {
            bool hi = (q & k) != 0;
            #pragma unroll
            for (int i = 0; i < 8; i++) {
                if (i < k) {
                    float send = hi ? p[i] : p[i + k];
                    float recv = __shfl_xor_sync(0xffffffffu, send, k);
                    p[i] = (hi ? p[i + k] : p[i]) + recv;
                }
            }
        }
        float sc = p[0];

        // ---- HOISTED h @ Wh half-matvec: independent of LN/argmax chain below ----
        float4 acch = make_float4(0.f, 0.f, 0.f, 0.f);
        #pragma unroll
        for (int it = 0; it < 32; it++) {
            int i = 2 * it + hh;
            float hv = sh[i];
            float4 wh4 = __ldg((const float4*)(Wh + i * HN + 4 * q));
            acch.x += hv * wh4.x; acch.y += hv * wh4.y;
            acch.z += hv * wh4.z; acch.w += hv * wh4.w;
        }

        int vd = (t < TN) ? vraw : 0;
        unsigned vm = __ballot_sync(0xffffffffu, vd);
        float has_edge = vm ? 1.f : 0.f;
        float logit = (vd ? sc : NEGV) * itc;

        // ---- fused single-pass LN (S1, S2, Sg reduced together) ----
        float x0 = sh[lane], x1 = sh[lane + 32];
        float e64 = (float)t / (float)TN;
        float e65 = has_edge;
        float s1 = x0 + x1;
        float s2 = x0 * x0 + x1 * x1;
        float sg = x0 * gsw0 + x1 * gsw1;
        if (lane == 0) {
            s1 += e64 + e65;
            s2 += e64 * e64 + e65 * e65;
            sg += e64 * gsw64 + e65 * gsw65;
        }
        #pragma unroll
        for (int o = 16; o; o >>= 1) {
            s1 += __shfl_xor_sync(~0u, s1, o);
            s2 += __shfl_xor_sync(~0u, s2, o);
            sg += __shfl_xor_sync(~0u, sg, o);
        }
        float mu = s1 * (1.f / 66.f);
        float var = s2 * (1.f / 66.f) - mu * mu;
        float rstd = rsqrtf(var + 1e-5f);
        float stop_logit = ((sg - mu * Gsum) * rstd + bsum + stop_b) * itc;

        // ---- argmax (first-max by row id) over 32 edge logits, then stop (strict >) ----
        float bv = logit; int bi = myrow;
        #pragma unroll
        for (int o = 16; o; o >>= 1) {
            float ov = __shfl_xor_sync(~0u, bv, o);
            int   oi = __shfl_xor_sync(~0u, bi, o);
            if (ov > bv || (ov == bv && oi < bi)) { bv = ov; bi = oi; }
        }
        int action; float chosen;
        if (stop_logit > bv) { action = DN; chosen = stop_logit; }
        else                 { action = bi; chosen = bv; }

        // ---- log-softmax denominator over 33 ----
        float m = fmaxf(bv, stop_logit);
        float es = expf(logit - m);
        #pragma unroll
        for (int o = 16; o; o >>= 1) es += __shfl_xor_sync(~0u, es, o);
        es += expf(stop_logit - m);
        float lp = chosen - (m + logf(es));

        bool chose_stop = (action == DN);
        int  a = chose_stop ? (DN - 1) : action;
        int  act_rec = chose_stop ? -1 : curr * DN + a;

        if (lane == 0) {
            outA[b * 9 + t] = (float)act_rec;
            outS[b * 9 + t] = lp;
        }
        lp_total += lp;
        if (chose_stop) break;
        nmoves++;

        // ---- advance: finish with sel @ Wk half, curr = tail (shuffle) ----
        int src_lane = (a >> 1) | ((a & 1) << 4);      // lane owning row a
        int tail = __shfl_sync(0xffffffffu, nb, src_lane);

        float4 selv = __ldg(&kb4[a * 16 + q]);          // chunk q of chosen row (L1-hot)
        if (hh == 0) *(float4*)(ss + 4 * q) = selv;
        __syncwarp();

        float4 acc = acch;
        #pragma unroll
        for (int it = 0; it < 32; it++) {
            int i = 2 * it + hh;
            float sv = ss[i];
            float4 wk4 = __ldg((const float4*)(Wk + i * HN + 4 * q));
            acc.x += sv * wk4.x; acc.y += sv * wk4.y;
            acc.z += sv * wk4.z; acc.w += sv * wk4.w;
        }
        acc.x += __shfl_xor_sync(0xffffffffu, acc.x, 16);
        acc.y += __shfl_xor_sync(0xffffffffu, acc.y, 16);
        acc.z += __shfl_xor_sync(0xffffffffu, acc.z, 16);
        acc.w += __shfl_xor_sync(0xffffffffu, acc.w, 16);
        __syncwarp();
        if (hh == 0) {
            float4 t4 = make_float4(tanhf(acc.x), tanhf(acc.y), tanhf(acc.z), tanhf(acc.w));
            *(float4*)(sh + 4 * q) = t4;
        }
        __syncwarp();
        curr = tail;
    }

    // ---- fill forced-stopped tail steps + totals ----
    if (lane == 0) {
        for (int tt = t + 1; tt <= TN; tt++) {
            outA[b * 9 + tt] = -1.f;
            outS[b * 9 + tt] = 0.f;
        }
        outTot[b] = lp_total;
        outNM[b]  = (float)nmoves;
    }
}

extern "C" void kernel_launch(void* const* d_in, const int* in_sizes, int n_in,
                              void* d_out, int out_size)
{
    const float* q     = (const float*)d_in[0];
    const int*   nbr   = (const int*)d_in[1];
    const int*   start = (const int*)d_in[2];
    const void*  ev    = (const void*)d_in[3];
    const float* keys  = (const float*)d_in[4];
    const float* Wi    = (const float*)d_in[5];
    const float* Wh    = (const float*)d_in[6];
    const float* Wk    = (const float*)d_in[7];
    const float* g     = (const float*)d_in[8];
    const float* be    = (const float*)d_in[9];
    const float* sw    = (const float*)d_in[10];
    const float* sb    = (const float*)d_in[11];
    const float* temp  = (const float*)d_in[12];
    float* out = (float*)d_out;

    dim3 grid(BN / 4);
    dim3 block(128);
    gfn_rollout_kernel<<<grid, block>>>(q, nbr, start, ev, keys,
                                        Wi, Wh, Wk, g, be, sw, sb, temp, out);
}